// round 1
// baseline (speedup 1.0000x reference)
#include <cuda_runtime.h>
#include <math.h>

#define NB   2048
#define NT   200
#define NE   64
#define NH1  64
#define NH2  16
#define NROWS (NB*NT)

// Scratch (device globals; no allocation allowed)
__device__ float g_x1[(size_t)NROWS * NH1];   // [B*T, 64]
__device__ float g_x2[(size_t)NROWS * NH2];   // [B*T, 16]
__device__ float g_sum1[NH1], g_sq1[NH1], g_mean1[NH1], g_rstd1[NH1];
__device__ float g_sum2[NH2], g_sq2[NH2], g_mean2[NH2], g_rstd2[NH2];

__global__ void k_zero() {
    int i = threadIdx.x;
    if (i < NH1) { g_sum1[i] = 0.f; g_sq1[i] = 0.f; }
    if (i < NH2) { g_sum2[i] = 0.f; g_sq2[i] = 0.f; }
}

// ---------------------------------------------------------------------------
// Kernel A: x1[b] = h[b] @ Wb(b) + cb(b);  accumulate per-feature sum/sumsq.
// Wb[e,j] = W1[64+e,j] - W1[128+e,j] + q[e]*W1[192+e,j]
// cb[j]   = b1[j] + sum_e q[e]*(W1[e,j] + W1[128+e,j])
// ---------------------------------------------------------------------------
__global__ __launch_bounds__(256, 2) void k_gemm1(
    const float* __restrict__ q, const float* __restrict__ hist,
    const float* __restrict__ W1, const float* __restrict__ b1)
{
    __shared__ float s_q[NE];
    __shared__ float s_cb[NH1];
    __shared__ __align__(16) float s_Wb[NE][NH1];
    __shared__ float s_h[100][65];            // pad 65 -> conflict-free h reads
    __shared__ float s_sum[NH1], s_sq[NH1];

    int b = blockIdx.x, tid = threadIdx.x;
    if (tid < NE) { s_q[tid] = q[b*NE + tid]; s_sum[tid] = 0.f; s_sq[tid] = 0.f; }
    __syncthreads();

    #pragma unroll
    for (int i = 0; i < 16; i++) {
        int idx = tid + 256*i;
        int e = idx >> 6, j = idx & 63;
        s_Wb[e][j] = W1[(64+e)*64 + j] - W1[(128+e)*64 + j] + s_q[e]*W1[(192+e)*64 + j];
    }
    if (tid < NH1) {
        float acc = b1[tid];
        #pragma unroll 8
        for (int e = 0; e < NE; e++)
            acc += s_q[e] * (W1[e*64 + tid] + W1[(128+e)*64 + tid]);
        s_cb[tid] = acc;
    }

    int tx = tid & 7, ty = tid >> 3;
    int j0 = tx * 8;
    int t0 = (ty < 25 ? ty : 0) * 4;
    float lsum[8], lsq[8];
    #pragma unroll
    for (int jj = 0; jj < 8; jj++) { lsum[jj] = 0.f; lsq[jj] = 0.f; }

    for (int c = 0; c < 2; c++) {
        __syncthreads();
        // stage 100x64 h tile (coalesced float4 reads, 2-way-conflict scalar STS)
        #pragma unroll
        for (int i = 0; i < 7; i++) {
            int f4 = tid + 256*i;
            if (f4 < 1600) {
                int t = f4 >> 4, e0 = (f4 & 15) << 2;
                const float4 v = *(const float4*)&hist[((size_t)(b*NT + c*100 + t))*NE + e0];
                s_h[t][e0]   = v.x; s_h[t][e0+1] = v.y;
                s_h[t][e0+2] = v.z; s_h[t][e0+3] = v.w;
            }
        }
        __syncthreads();
        if (tid < 200) {
            float acc[4][8];
            #pragma unroll
            for (int it = 0; it < 4; it++)
                #pragma unroll
                for (int jj = 0; jj < 8; jj++) acc[it][jj] = 0.f;

            #pragma unroll 8
            for (int e = 0; e < NE; e++) {
                float4 w0 = *(const float4*)&s_Wb[e][j0];
                float4 w1 = *(const float4*)&s_Wb[e][j0+4];
                float wa[8] = {w0.x,w0.y,w0.z,w0.w,w1.x,w1.y,w1.z,w1.w};
                float ha[4];
                #pragma unroll
                for (int it = 0; it < 4; it++) ha[it] = s_h[t0+it][e];
                #pragma unroll
                for (int it = 0; it < 4; it++)
                    #pragma unroll
                    for (int jj = 0; jj < 8; jj++)
                        acc[it][jj] = fmaf(ha[it], wa[jj], acc[it][jj]);
            }
            #pragma unroll
            for (int it = 0; it < 4; it++) {
                int row = b*NT + c*100 + t0 + it;
                float v[8];
                #pragma unroll
                for (int jj = 0; jj < 8; jj++) {
                    v[jj] = acc[it][jj] + s_cb[j0+jj];
                    lsum[jj] += v[jj];
                    lsq[jj]  += v[jj]*v[jj];
                }
                *(float4*)&g_x1[(size_t)row*NH1 + j0]     = make_float4(v[0],v[1],v[2],v[3]);
                *(float4*)&g_x1[(size_t)row*NH1 + j0 + 4] = make_float4(v[4],v[5],v[6],v[7]);
            }
        }
    }
    // reduce over the 4 t-groups within each warp (lane bits 3,4), tx preserved
    #pragma unroll
    for (int jj = 0; jj < 8; jj++) {
        #pragma unroll
        for (int off = 8; off <= 16; off <<= 1) {
            lsum[jj] += __shfl_xor_sync(0xffffffffu, lsum[jj], off);
            lsq[jj]  += __shfl_xor_sync(0xffffffffu, lsq[jj],  off);
        }
    }
    if ((tid & 31) < 8) {
        int jb = (tid & 7) * 8;
        #pragma unroll
        for (int jj = 0; jj < 8; jj++) {
            atomicAdd(&s_sum[jb+jj], lsum[jj]);
            atomicAdd(&s_sq[jb+jj],  lsq[jj]);
        }
    }
    __syncthreads();
    if (tid < NH1) {
        atomicAdd(&g_sum1[tid], s_sum[tid]);
        atomicAdd(&g_sq1[tid],  s_sq[tid]);
    }
}

__global__ void k_fin1() {
    int j = threadIdx.x;
    if (j < NH1) {
        float n = (float)NROWS;
        float m = g_sum1[j] / n;
        float v = g_sq1[j] / n - m*m;
        g_mean1[j] = m;
        g_rstd1[j] = rsqrtf(v + 1e-8f);
    }
}

// ---------------------------------------------------------------------------
// Kernel B: x2 = dice1(x1) @ W2 + b2;  accumulate layer-2 stats.
// 128 rows per block.
// ---------------------------------------------------------------------------
__global__ __launch_bounds__(256, 2) void k_gemm2(
    const float* __restrict__ W2, const float* __restrict__ b2,
    const float* __restrict__ alpha1)
{
    __shared__ __align__(16) float s_x[128][68];    // pad 68 -> conflict-free f4
    __shared__ __align__(16) float s_W2T[16][68];
    __shared__ float s_m1[64], s_r1[64], s_a1[64], s_b2[16];
    __shared__ float s_sum[16], s_sq[16];

    int tid = threadIdx.x;
    int row0 = blockIdx.x * 128;
    if (tid < 64) { s_m1[tid] = g_mean1[tid]; s_r1[tid] = g_rstd1[tid]; s_a1[tid] = alpha1[tid]; }
    if (tid < 16) { s_b2[tid] = b2[tid]; s_sum[tid] = 0.f; s_sq[tid] = 0.f; }
    #pragma unroll
    for (int i = 0; i < 4; i++) {
        int idx = tid + 256*i;
        if (idx < 1024) {
            int e = idx >> 4, cc = idx & 15;
            s_W2T[cc][e] = W2[idx];
        }
    }
    __syncthreads();

    // stage 128x64 x1 tile with dice1 applied
    #pragma unroll
    for (int i = 0; i < 8; i++) {
        int f4 = tid + 256*i;
        int r = f4 >> 4, e0 = (f4 & 15) << 2;
        float4 v = *(const float4*)&g_x1[(size_t)(row0 + r)*64 + e0];
        float vv[4] = {v.x, v.y, v.z, v.w};
        #pragma unroll
        for (int u = 0; u < 4; u++) {
            int j = e0 + u;
            float xn = (vv[u] - s_m1[j]) * s_r1[j];
            float p  = __fdividef(1.f, 1.f + __expf(-xn));
            float a  = s_a1[j];
            vv[u] = vv[u] * (a + (1.f - a) * p);
        }
        *(float4*)&s_x[r][e0] = make_float4(vv[0], vv[1], vv[2], vv[3]);
    }
    __syncthreads();

    int tx = tid & 7, rt = tid >> 3;
    int c0 = tx * 2;
    float acc[4][2];
    #pragma unroll
    for (int k = 0; k < 4; k++) { acc[k][0] = 0.f; acc[k][1] = 0.f; }

    #pragma unroll 4
    for (int ec = 0; ec < 16; ec++) {
        int e0 = ec * 4;
        float4 wv0 = *(const float4*)&s_W2T[c0][e0];
        float4 wv1 = *(const float4*)&s_W2T[c0+1][e0];
        #pragma unroll
        for (int k = 0; k < 4; k++) {
            float4 xv = *(const float4*)&s_x[rt + 32*k][e0];
            acc[k][0] = fmaf(xv.x, wv0.x, fmaf(xv.y, wv0.y, fmaf(xv.z, wv0.z, fmaf(xv.w, wv0.w, acc[k][0]))));
            acc[k][1] = fmaf(xv.x, wv1.x, fmaf(xv.y, wv1.y, fmaf(xv.z, wv1.z, fmaf(xv.w, wv1.w, acc[k][1]))));
        }
    }

    float lps[2] = {0.f, 0.f}, lpq[2] = {0.f, 0.f};
    #pragma unroll
    for (int k = 0; k < 4; k++) {
        #pragma unroll
        for (int cc = 0; cc < 2; cc++) {
            float val = acc[k][cc] + s_b2[c0+cc];
            g_x2[(size_t)(row0 + rt + 32*k)*16 + c0 + cc] = val;
            lps[cc] += val;
            lpq[cc] += val*val;
        }
    }
    #pragma unroll
    for (int cc = 0; cc < 2; cc++) {
        #pragma unroll
        for (int off = 8; off <= 16; off <<= 1) {
            lps[cc] += __shfl_xor_sync(0xffffffffu, lps[cc], off);
            lpq[cc] += __shfl_xor_sync(0xffffffffu, lpq[cc], off);
        }
    }
    if ((tid & 31) < 8) {
        int cb = (tid & 7) * 2;
        atomicAdd(&s_sum[cb],   lps[0]); atomicAdd(&s_sum[cb+1], lps[1]);
        atomicAdd(&s_sq[cb],    lpq[0]); atomicAdd(&s_sq[cb+1],  lpq[1]);
    }
    __syncthreads();
    if (tid < 16) {
        atomicAdd(&g_sum2[tid], s_sum[tid]);
        atomicAdd(&g_sq2[tid],  s_sq[tid]);
    }
}

__global__ void k_fin2() {
    int j = threadIdx.x;
    if (j < NH2) {
        float n = (float)NROWS;
        float m = g_sum2[j] / n;
        float v = g_sq2[j] / n - m*m;
        g_mean2[j] = m;
        g_rstd2[j] = rsqrtf(v + 1e-8f);
    }
}

// ---------------------------------------------------------------------------
// Kernel C: dice2 -> mask -> softmax over T (per h) -> score @ hist -> out
// One block per batch.
// ---------------------------------------------------------------------------
__global__ __launch_bounds__(256, 2) void k_final(
    const float* __restrict__ hist, const int* __restrict__ lens,
    const float* __restrict__ alpha2, float* __restrict__ out)
{
    __shared__ __align__(16) float s_logit[200][16];
    __shared__ __align__(16) float s_hist[50][64];
    __shared__ float s_inv[16];
    __shared__ float s_m2[16], s_r2[16], s_a2[16];

    int b = blockIdx.x, tid = threadIdx.x;
    if (tid < 16) { s_m2[tid] = g_mean2[tid]; s_r2[tid] = g_rstd2[tid]; s_a2[tid] = alpha2[tid]; }
    __syncthreads();
    int len = lens[b];

    // stage logits with dice2 + mask (mask: t < len -> 1e-9)
    #pragma unroll
    for (int i = 0; i < 4; i++) {
        int f4 = tid + 256*i;
        if (f4 < 800) {
            int r = f4 >> 2, h0 = (f4 & 3) << 2;
            float4 v = *(const float4*)&g_x2[(size_t)(b*NT + r)*16 + h0];
            float vv[4] = {v.x, v.y, v.z, v.w};
            #pragma unroll
            for (int u = 0; u < 4; u++) {
                int hh = h0 + u;
                float xn = (vv[u] - s_m2[hh]) * s_r2[hh];
                float p  = __fdividef(1.f, 1.f + __expf(-xn));
                float a  = s_a2[hh];
                float d  = vv[u] * (a + (1.f - a) * p);
                vv[u] = (r < len) ? 1e-9f : d;
            }
            *(float4*)&s_logit[r][h0] = make_float4(vv[0], vv[1], vv[2], vv[3]);
        }
    }
    __syncthreads();

    // 16 softmaxes over T=200, one per half-warp-of-16
    int g = tid >> 4, l16 = tid & 15;
    float m = -1e30f;
    for (int t = l16; t < NT; t += 16) m = fmaxf(m, s_logit[t][g]);
    #pragma unroll
    for (int off = 1; off < 16; off <<= 1)
        m = fmaxf(m, __shfl_xor_sync(0xffffffffu, m, off, 16));
    float s = 0.f;
    for (int t = l16; t < NT; t += 16) {
        float ev = __expf(s_logit[t][g] - m);
        s_logit[t][g] = ev;
        s += ev;
    }
    #pragma unroll
    for (int off = 1; off < 16; off <<= 1)
        s += __shfl_xor_sync(0xffffffffu, s, off, 16);
    if (l16 == 0) s_inv[g] = __fdividef(1.f, s);

    // out[b,h,e] = (sum_t exp_t[h] * hist[b,t,e]) * inv[h]
    int e = tid & 63, hg = tid >> 6;
    float acc[4] = {0.f, 0.f, 0.f, 0.f};
    for (int tc = 0; tc < 4; tc++) {
        __syncthreads();
        #pragma unroll
        for (int i = 0; i < 4; i++) {
            int f4 = tid + 256*i;
            if (f4 < 800) {
                int tt = f4 >> 4, e0 = (f4 & 15) << 2;
                *(float4*)&s_hist[tt][e0] =
                    *(const float4*)&hist[(size_t)(b*NT + tc*50 + tt)*64 + e0];
            }
        }
        __syncthreads();
        #pragma unroll 2
        for (int t = 0; t < 50; t++) {
            float4 sc = *(const float4*)&s_logit[tc*50 + t][hg*4];
            float hv = s_hist[t][e];
            acc[0] = fmaf(sc.x, hv, acc[0]);
            acc[1] = fmaf(sc.y, hv, acc[1]);
            acc[2] = fmaf(sc.z, hv, acc[2]);
            acc[3] = fmaf(sc.w, hv, acc[3]);
        }
    }
    float4 iv = *(const float4*)&s_inv[hg*4];
    float ia[4] = {iv.x, iv.y, iv.z, iv.w};
    #pragma unroll
    for (int k = 0; k < 4; k++)
        out[(size_t)(b*NH2 + hg*4 + k)*NE + e] = acc[k] * ia[k];
}

extern "C" void kernel_launch(void* const* d_in, const int* in_sizes, int n_in,
                              void* d_out, int out_size)
{
    const float* q    = (const float*)d_in[0];
    const float* hist = (const float*)d_in[1];
    const int*   lens = (const int*)  d_in[2];
    const float* W1   = (const float*)d_in[3];
    const float* b1   = (const float*)d_in[4];
    const float* a1   = (const float*)d_in[5];
    const float* W2   = (const float*)d_in[6];
    const float* b2   = (const float*)d_in[7];
    const float* a2   = (const float*)d_in[8];
    float* out = (float*)d_out;

    k_zero<<<1, 64>>>();
    k_gemm1<<<NB, 256>>>(q, hist, W1, b1);
    k_fin1<<<1, 64>>>();
    k_gemm2<<<NROWS/128, 256>>>(W2, b2, a1);
    k_fin2<<<1, 16>>>();
    k_final<<<NB, 256>>>(hist, lens, a2, out);
}

// round 2
// speedup vs baseline: 1.1194x; 1.1194x over previous
#include <cuda_runtime.h>
#include <math.h>

#define NB   2048
#define NT   200
#define NE   64
#define NH1  64
#define NH2  16
#define NROWS (NB*NT)

// Scratch (device globals; no allocation allowed)
__device__ float g_x1[(size_t)NROWS * NH1];   // [B*T, 64]
__device__ float g_x2[(size_t)NROWS * NH2];   // [B*T, 16]
__device__ float g_sum1[NH1], g_sq1[NH1], g_mean1[NH1], g_rstd1[NH1];
__device__ float g_sum2[NH2], g_sq2[NH2], g_mean2[NH2], g_rstd2[NH2];

__global__ void k_zero() {
    int i = threadIdx.x;
    if (i < NH1) { g_sum1[i] = 0.f; g_sq1[i] = 0.f; }
    if (i < NH2) { g_sum2[i] = 0.f; g_sq2[i] = 0.f; }
}

// ---------------------------------------------------------------------------
// Kernel A: x1[b] = h[b] @ Wb(b) + cb(b);  accumulate per-feature sum/sumsq.
// Wb[e,j] = W1[64+e,j] - W1[128+e,j] + q[e]*W1[192+e,j]
// cb[j]   = b1[j] + sum_e q[e]*(W1[e,j] + W1[128+e,j])
// All 256 threads compute: tx(8) x-cols of 8, ty(32) rows of up to 7.
// K is split into two 32-wide chunks staged in smem; accs persist.
// ---------------------------------------------------------------------------
__global__ __launch_bounds__(256, 2) void k_gemm1(
    const float* __restrict__ q, const float* __restrict__ hist,
    const float* __restrict__ W1, const float* __restrict__ b1)
{
    __shared__ float s_q[NE];
    __shared__ float s_cb[NH1];
    __shared__ __align__(16) float s_Wb[NE][NH1];
    __shared__ __align__(16) float s_h[NT][36];      // 32-wide e-chunk, pad->36
    __shared__ float s_sum[NH1], s_sq[NH1];

    int b = blockIdx.x, tid = threadIdx.x;
    if (tid < NE) { s_q[tid] = q[b*NE + tid]; s_sum[tid] = 0.f; s_sq[tid] = 0.f; }
    __syncthreads();

    #pragma unroll
    for (int i = 0; i < 16; i++) {
        int idx = tid + 256*i;
        int e = idx >> 6, j = idx & 63;
        s_Wb[e][j] = W1[(64+e)*64 + j] - W1[(128+e)*64 + j] + s_q[e]*W1[(192+e)*64 + j];
    }
    if (tid < NH1) {
        float acc = b1[tid];
        #pragma unroll 8
        for (int e = 0; e < NE; e++)
            acc += s_q[e] * (W1[e*64 + tid] + W1[(128+e)*64 + tid]);
        s_cb[tid] = acc;
    }

    int tx = tid & 7, ty = tid >> 3;
    int j0 = tx * 8;
    bool has7 = (ty < 8);                            // rows 192..199

    float acc[7][8];
    #pragma unroll
    for (int k = 0; k < 7; k++)
        #pragma unroll
        for (int jj = 0; jj < 8; jj++) acc[k][jj] = 0.f;

    for (int c = 0; c < 2; c++) {
        __syncthreads();
        // stage 200 x 32 chunk of h (coalesced float4)
        #pragma unroll
        for (int i = 0; i < 7; i++) {
            int f4 = tid + 256*i;
            if (f4 < 1600) {
                int t = f4 >> 3, e0 = (f4 & 7) << 2;
                *(float4*)&s_h[t][e0] =
                    *(const float4*)&hist[((size_t)(b*NT + t))*NE + c*32 + e0];
            }
        }
        __syncthreads();

        #pragma unroll 4
        for (int e = 0; e < 32; e++) {
            float4 w0 = *(const float4*)&s_Wb[c*32 + e][j0];
            float4 w1 = *(const float4*)&s_Wb[c*32 + e][j0 + 4];
            float wa[8] = {w0.x,w0.y,w0.z,w0.w,w1.x,w1.y,w1.z,w1.w};
            float ha[7];
            #pragma unroll
            for (int k = 0; k < 6; k++) ha[k] = s_h[ty + 32*k][e];
            ha[6] = has7 ? s_h[192 + ty][e] : 0.f;
            #pragma unroll
            for (int k = 0; k < 7; k++)
                #pragma unroll
                for (int jj = 0; jj < 8; jj++)
                    acc[k][jj] = fmaf(ha[k], wa[jj], acc[k][jj]);
        }
    }

    // epilogue: bias add, stats, single write-out
    float lsum[8], lsq[8];
    #pragma unroll
    for (int jj = 0; jj < 8; jj++) { lsum[jj] = 0.f; lsq[jj] = 0.f; }

    #pragma unroll
    for (int k = 0; k < 7; k++) {
        if (k == 6 && !has7) break;
        int t = ty + 32*k;
        float v[8];
        #pragma unroll
        for (int jj = 0; jj < 8; jj++) {
            v[jj] = acc[k][jj] + s_cb[j0 + jj];
            lsum[jj] += v[jj];
            lsq[jj]  += v[jj]*v[jj];
        }
        *(float4*)&g_x1[(size_t)(b*NT + t)*NH1 + j0]     = make_float4(v[0],v[1],v[2],v[3]);
        *(float4*)&g_x1[(size_t)(b*NT + t)*NH1 + j0 + 4] = make_float4(v[4],v[5],v[6],v[7]);
    }

    // reduce across ty within warp (lane bits 3,4), tx preserved
    #pragma unroll
    for (int jj = 0; jj < 8; jj++) {
        #pragma unroll
        for (int off = 8; off <= 16; off <<= 1) {
            lsum[jj] += __shfl_xor_sync(0xffffffffu, lsum[jj], off);
            lsq[jj]  += __shfl_xor_sync(0xffffffffu, lsq[jj],  off);
        }
    }
    if ((tid & 31) < 8) {
        int jb = (tid & 7) * 8;
        #pragma unroll
        for (int jj = 0; jj < 8; jj++) {
            atomicAdd(&s_sum[jb+jj], lsum[jj]);
            atomicAdd(&s_sq[jb+jj],  lsq[jj]);
        }
    }
    __syncthreads();
    if (tid < NH1) {
        atomicAdd(&g_sum1[tid], s_sum[tid]);
        atomicAdd(&g_sq1[tid],  s_sq[tid]);
    }
}

__global__ void k_fin1() {
    int j = threadIdx.x;
    if (j < NH1) {
        float n = (float)NROWS;
        float m = g_sum1[j] / n;
        float v = g_sq1[j] / n - m*m;
        g_mean1[j] = m;
        g_rstd1[j] = rsqrtf(v + 1e-8f);
    }
}

// ---------------------------------------------------------------------------
// Kernel B: x2 = dice1(x1) @ W2 + b2;  accumulate layer-2 stats.
// 128 rows per block; occupancy 4.
// ---------------------------------------------------------------------------
__global__ __launch_bounds__(256, 4) void k_gemm2(
    const float* __restrict__ W2, const float* __restrict__ b2,
    const float* __restrict__ alpha1)
{
    __shared__ __align__(16) float s_x[128][68];    // pad 68 -> conflict-free f4
    __shared__ __align__(16) float s_W2T[16][68];
    __shared__ float s_m1[64], s_r1[64], s_a1[64], s_b2[16];
    __shared__ float s_sum[16], s_sq[16];

    int tid = threadIdx.x;
    int row0 = blockIdx.x * 128;
    if (tid < 64) { s_m1[tid] = g_mean1[tid]; s_r1[tid] = g_rstd1[tid]; s_a1[tid] = alpha1[tid]; }
    if (tid < 16) { s_b2[tid] = b2[tid]; s_sum[tid] = 0.f; s_sq[tid] = 0.f; }
    #pragma unroll
    for (int i = 0; i < 4; i++) {
        int idx = tid + 256*i;
        if (idx < 1024) {
            int e = idx >> 4, cc = idx & 15;
            s_W2T[cc][e] = W2[idx];
        }
    }
    __syncthreads();

    // stage 128x64 x1 tile with dice1 applied
    #pragma unroll 2
    for (int i = 0; i < 8; i++) {
        int f4 = tid + 256*i;
        int r = f4 >> 4, e0 = (f4 & 15) << 2;
        float4 v = *(const float4*)&g_x1[(size_t)(row0 + r)*64 + e0];
        float vv[4] = {v.x, v.y, v.z, v.w};
        #pragma unroll
        for (int u = 0; u < 4; u++) {
            int j = e0 + u;
            float xn = (vv[u] - s_m1[j]) * s_r1[j];
            float p  = __fdividef(1.f, 1.f + __expf(-xn));
            float a  = s_a1[j];
            vv[u] = vv[u] * (a + (1.f - a) * p);
        }
        *(float4*)&s_x[r][e0] = make_float4(vv[0], vv[1], vv[2], vv[3]);
    }
    __syncthreads();

    int tx = tid & 7, rt = tid >> 3;
    int c0 = tx * 2;
    float acc[4][2];
    #pragma unroll
    for (int k = 0; k < 4; k++) { acc[k][0] = 0.f; acc[k][1] = 0.f; }

    #pragma unroll 4
    for (int ec = 0; ec < 16; ec++) {
        int e0 = ec * 4;
        float4 wv0 = *(const float4*)&s_W2T[c0][e0];
        float4 wv1 = *(const float4*)&s_W2T[c0+1][e0];
        #pragma unroll
        for (int k = 0; k < 4; k++) {
            float4 xv = *(const float4*)&s_x[rt + 32*k][e0];
            acc[k][0] = fmaf(xv.x, wv0.x, fmaf(xv.y, wv0.y, fmaf(xv.z, wv0.z, fmaf(xv.w, wv0.w, acc[k][0]))));
            acc[k][1] = fmaf(xv.x, wv1.x, fmaf(xv.y, wv1.y, fmaf(xv.z, wv1.z, fmaf(xv.w, wv1.w, acc[k][1]))));
        }
    }

    float lps[2] = {0.f, 0.f}, lpq[2] = {0.f, 0.f};
    #pragma unroll
    for (int k = 0; k < 4; k++) {
        #pragma unroll
        for (int cc = 0; cc < 2; cc++) {
            float val = acc[k][cc] + s_b2[c0+cc];
            g_x2[(size_t)(row0 + rt + 32*k)*16 + c0 + cc] = val;
            lps[cc] += val;
            lpq[cc] += val*val;
        }
    }
    #pragma unroll
    for (int cc = 0; cc < 2; cc++) {
        #pragma unroll
        for (int off = 8; off <= 16; off <<= 1) {
            lps[cc] += __shfl_xor_sync(0xffffffffu, lps[cc], off);
            lpq[cc] += __shfl_xor_sync(0xffffffffu, lpq[cc], off);
        }
    }
    if ((tid & 31) < 8) {
        int cb = (tid & 7) * 2;
        atomicAdd(&s_sum[cb],   lps[0]); atomicAdd(&s_sum[cb+1], lps[1]);
        atomicAdd(&s_sq[cb],    lpq[0]); atomicAdd(&s_sq[cb+1],  lpq[1]);
    }
    __syncthreads();
    if (tid < 16) {
        atomicAdd(&g_sum2[tid], s_sum[tid]);
        atomicAdd(&g_sq2[tid],  s_sq[tid]);
    }
}

__global__ void k_fin2() {
    int j = threadIdx.x;
    if (j < NH2) {
        float n = (float)NROWS;
        float m = g_sum2[j] / n;
        float v = g_sq2[j] / n - m*m;
        g_mean2[j] = m;
        g_rstd2[j] = rsqrtf(v + 1e-8f);
    }
}

// ---------------------------------------------------------------------------
// Kernel C: dice2 -> mask -> softmax over T (per h) -> score @ hist -> out
// One block per batch; occupancy 4; logits padded to 20 floats/row.
// ---------------------------------------------------------------------------
__global__ __launch_bounds__(256, 4) void k_final(
    const float* __restrict__ hist, const int* __restrict__ lens,
    const float* __restrict__ alpha2, float* __restrict__ out)
{
    __shared__ __align__(16) float s_logit[200][20];
    __shared__ __align__(16) float s_hist[50][64];
    __shared__ float s_inv[16];
    __shared__ float s_m2[16], s_r2[16], s_a2[16];

    int b = blockIdx.x, tid = threadIdx.x;
    if (tid < 16) { s_m2[tid] = g_mean2[tid]; s_r2[tid] = g_rstd2[tid]; s_a2[tid] = alpha2[tid]; }
    __syncthreads();
    int len = lens[b];

    // stage logits with dice2 + mask (mask: t < len -> 1e-9)
    #pragma unroll
    for (int i = 0; i < 4; i++) {
        int f4 = tid + 256*i;
        if (f4 < 800) {
            int r = f4 >> 2, h0 = (f4 & 3) << 2;
            float4 v = *(const float4*)&g_x2[(size_t)(b*NT + r)*16 + h0];
            float vv[4] = {v.x, v.y, v.z, v.w};
            #pragma unroll
            for (int u = 0; u < 4; u++) {
                int hh = h0 + u;
                float xn = (vv[u] - s_m2[hh]) * s_r2[hh];
                float p  = __fdividef(1.f, 1.f + __expf(-xn));
                float a  = s_a2[hh];
                float d  = vv[u] * (a + (1.f - a) * p);
                vv[u] = (r < len) ? 1e-9f : d;
            }
            *(float4*)&s_logit[r][h0] = make_float4(vv[0], vv[1], vv[2], vv[3]);
        }
    }
    __syncthreads();

    // 16 softmaxes over T=200, one per half-warp-of-16
    int g = tid >> 4, l16 = tid & 15;
    float m = -1e30f;
    for (int t = l16; t < NT; t += 16) m = fmaxf(m, s_logit[t][g]);
    #pragma unroll
    for (int off = 1; off < 16; off <<= 1)
        m = fmaxf(m, __shfl_xor_sync(0xffffffffu, m, off, 16));
    float s = 0.f;
    for (int t = l16; t < NT; t += 16) {
        float ev = __expf(s_logit[t][g] - m);
        s_logit[t][g] = ev;
        s += ev;
    }
    #pragma unroll
    for (int off = 1; off < 16; off <<= 1)
        s += __shfl_xor_sync(0xffffffffu, s, off, 16);
    if (l16 == 0) s_inv[g] = __fdividef(1.f, s);

    // out[b,h,e] = (sum_t exp_t[h] * hist[b,t,e]) * inv[h]
    int e = tid & 63, hg = tid >> 6;
    float acc[4] = {0.f, 0.f, 0.f, 0.f};
    for (int tc = 0; tc < 4; tc++) {
        __syncthreads();
        #pragma unroll
        for (int i = 0; i < 4; i++) {
            int f4 = tid + 256*i;
            if (f4 < 800) {
                int tt = f4 >> 4, e0 = (f4 & 15) << 2;
                *(float4*)&s_hist[tt][e0] =
                    *(const float4*)&hist[(size_t)(b*NT + tc*50 + tt)*64 + e0];
            }
        }
        __syncthreads();
        #pragma unroll 2
        for (int t = 0; t < 50; t++) {
            float4 sc = *(const float4*)&s_logit[tc*50 + t][hg*4];
            float hv = s_hist[t][e];
            acc[0] = fmaf(sc.x, hv, acc[0]);
            acc[1] = fmaf(sc.y, hv, acc[1]);
            acc[2] = fmaf(sc.z, hv, acc[2]);
            acc[3] = fmaf(sc.w, hv, acc[3]);
        }
    }
    float4 iv = *(const float4*)&s_inv[hg*4];
    float ia[4] = {iv.x, iv.y, iv.z, iv.w};
    #pragma unroll
    for (int k = 0; k < 4; k++)
        out[(size_t)(b*NH2 + hg*4 + k)*NE + e] = acc[k] * ia[k];
}

extern "C" void kernel_launch(void* const* d_in, const int* in_sizes, int n_in,
                              void* d_out, int out_size)
{
    const float* q    = (const float*)d_in[0];
    const float* hist = (const float*)d_in[1];
    const int*   lens = (const int*)  d_in[2];
    const float* W1   = (const float*)d_in[3];
    const float* b1   = (const float*)d_in[4];
    const float* a1   = (const float*)d_in[5];
    const float* W2   = (const float*)d_in[6];
    const float* b2   = (const float*)d_in[7];
    const float* a2   = (const float*)d_in[8];
    float* out = (float*)d_out;

    k_zero<<<1, 64>>>();
    k_gemm1<<<NB, 256>>>(q, hist, W1, b1);
    k_fin1<<<1, 64>>>();
    k_gemm2<<<NROWS/128, 256>>>(W2, b2, a1);
    k_fin2<<<1, 16>>>();
    k_final<<<NB, 256>>>(hist, lens, a2, out);
}